// round 14
// baseline (speedup 1.0000x reference)
#include <cuda_runtime.h>
#include <cuda_pipeline.h>

// ---------------------------------------------------------------------------
// out[i, :32] = sum_m sum_{j: t2m_j <= t1_i} (Q_i . Km_j) * Vm_j[:32]
//   Q = mlp3(m1, WQ); K_m = mlp3(m_m, WK[m]); V_m = m_m[:, :32]
// ---------------------------------------------------------------------------

#define T1        4096
#define TOTK      22528            // 4096+6144+8192+4096
#define CBLK      64               // key block size
#define NOBLK     352              // total key blocks (64+96+128+64)
#define NSTATE    356              // exclusive prefix states (nb+1 per modality)
#define NTILE     128              // query tiles of 32

typedef unsigned long long u64;

__device__ __forceinline__ u64 pk2(float lo, float hi) {
    u64 r; asm("mov.b64 %0,{%1,%2};" : "=l"(r) : "f"(lo), "f"(hi)); return r;
}
__device__ __forceinline__ void upk2(u64 v, float& lo, float& hi) {
    asm("mov.b64 {%0,%1},%2;" : "=f"(lo), "=f"(hi) : "l"(v));
}
__device__ __forceinline__ void ffma2(u64& d, u64 a, u64 b) {
    asm("fma.rn.f32x2 %0,%1,%2,%0;" : "+l"(d) : "l"(a), "l"(b));
}

// scratch (no allocations allowed)
__device__ float g_Q[T1 * 64];
__device__ float g_K[TOTK * 64];
__device__ float g_t2[TOTK];
__device__ float g_O[NOBLK * 2048];    // per-block sums  K^T V  (64 x 32)
__device__ float g_S[NSTATE * 2048];   // exclusive prefix states
__device__ int   g_cnt[NTILE][4][2];

__constant__ int c_T2[4]    = {4096, 6144, 8192, 4096};
__constant__ int c_KOFF[4]  = {0, 4096, 10240, 18432};
__constant__ int c_NB[4]    = {64, 96, 128, 64};
__constant__ int c_OOFF[5]  = {0, 64, 160, 288, 352};
__constant__ int c_SOFF[4]  = {0, 65, 162, 291};

// ---------------------------------------------------------------------------
// Kernel 1: fused 3-layer MLP + (for K tasks) blocksum O_b = K^T V, t2.
// 256 threads, 64-row tile, 4x4 per-thread tiles. Weights double-buffered
// in smem and prefetched with cp.async (zero register cost) -> regs ~80,
// ~24 warps/SM instead of 12.
// ---------------------------------------------------------------------------
__global__ void __launch_bounds__(256) mlp_kernel(
    const float* __restrict__ m1, const float* __restrict__ m2,
    const float* __restrict__ m3, const float* __restrict__ m4,
    const float* __restrict__ WQ_w, const float* __restrict__ WQ_b,
    const float* __restrict__ WK_w, const float* __restrict__ WK_b)
{
    __shared__ float Hs[64][68];      // [k][row] transposed activations; later V [j][e]
    __shared__ float Ws[2][64][68];   // double-buffered weights [k][col]; Ws[1] later K [j][d]
    __shared__ float bsAll[192];      // all 3 bias rows

    const int task = blockIdx.y;
    const int rowsTab[5] = {4096, 4096, 6144, 8192, 4096};
    const int rows = rowsTab[task];
    const int row0 = blockIdx.x * 64;
    if (row0 >= rows) return;

    const float* X;
    if (task <= 1)      X = m1;
    else if (task == 2) X = m2;
    else if (task == 3) X = m3;
    else                X = m4;

    const float* Wb; const float* bb; float* out;
    if (task == 0) { Wb = WQ_w; bb = WQ_b; out = g_Q; }
    else {
        int m = task - 1;
        Wb = WK_w + m * 3 * 4096;
        bb = WK_b + m * 192;
        out = g_K + c_KOFF[m] * 64;
    }

    const int tid = threadIdx.x;

    // prologue: layer-0 weights via cp.async, X tile transposed, biases, t2
    #pragma unroll
    for (int q = 0; q < 4; q++) {
        int fi = (tid + q * 256) * 4;
        __pipeline_memcpy_async(&Ws[0][fi >> 6][fi & 63], Wb + fi, 16);
    }
    __pipeline_commit();   // #0: Ws[0]

    for (int idx = tid; idx < 4096; idx += 256) {
        int r = idx >> 6, c = idx & 63;
        Hs[c][r] = X[(row0 + r) * 64 + c];
    }
    if (tid < 192) bsAll[tid] = bb[tid];
    if (task > 0 && tid < 64)
        g_t2[c_KOFF[task - 1] + row0 + tid] = X[(row0 + tid) * 64 + 63];

    const int r0 = (tid & 15) * 4;     // 16 row groups of 4
    const int c0 = (tid >> 4) * 4;     // 16 col groups of 4
    float vreg[8];

    for (int l = 0; l < 3; l++) {
        if (l < 2) {
            // prefetch next layer's weights into the other buffer (no regs)
            #pragma unroll
            for (int q = 0; q < 4; q++) {
                int fi = (tid + q * 256) * 4;
                __pipeline_memcpy_async(&Ws[l ^ 1][fi >> 6][fi & 63],
                                        Wb + (l + 1) * 4096 + fi, 16);
            }
            __pipeline_commit();   // #(l+1)
        } else if (task > 0) {
            #pragma unroll
            for (int q = 0; q < 8; q++) {
                int idx = tid + q * 256;
                vreg[q] = X[(row0 + (idx >> 5)) * 64 + (idx & 31)];
            }
        }
        // wait for THIS layer's buffer: l=0,1 -> one outstanding allowed; l=2 -> none
        __pipeline_wait_prior(l < 2 ? 1 : 0);
        __syncthreads();

        const float (*W)[68] = Ws[l & 1];

        u64 acc[4][2];   // [row][col-pair]
        #pragma unroll
        for (int rr = 0; rr < 4; rr++)
            #pragma unroll
            for (int cp = 0; cp < 2; cp++)
                acc[rr][cp] = pk2(bsAll[l * 64 + c0 + 2 * cp],
                                  bsAll[l * 64 + c0 + 2 * cp + 1]);

        #pragma unroll 8
        for (int k = 0; k < 64; k++) {
            float4 h = *(const float4*)&Hs[k][r0];
            ulonglong2 w2 = *(const ulonglong2*)&W[k][c0];
            u64 hd0 = pk2(h.x, h.x), hd1 = pk2(h.y, h.y);
            u64 hd2 = pk2(h.z, h.z), hd3 = pk2(h.w, h.w);
            ffma2(acc[0][0], hd0, w2.x); ffma2(acc[0][1], hd0, w2.y);
            ffma2(acc[1][0], hd1, w2.x); ffma2(acc[1][1], hd1, w2.y);
            ffma2(acc[2][0], hd2, w2.x); ffma2(acc[2][1], hd2, w2.y);
            ffma2(acc[3][0], hd3, w2.x); ffma2(acc[3][1], hd3, w2.y);
        }

        float a[4][4];
        #pragma unroll
        for (int rr = 0; rr < 4; rr++)
            #pragma unroll
            for (int cp = 0; cp < 2; cp++)
                upk2(acc[rr][cp], a[rr][2 * cp], a[rr][2 * cp + 1]);

        if (l < 2) {
            #pragma unroll
            for (int rr = 0; rr < 4; rr++)
                #pragma unroll
                for (int cc = 0; cc < 4; cc++) a[rr][cc] = fmaxf(a[rr][cc], 0.0f);
        }
        __syncthreads();   // Hs/W reads for layer l done

        if (l < 2) {
            #pragma unroll
            for (int cc = 0; cc < 4; cc++) {
                float4 v = make_float4(a[0][cc], a[1][cc], a[2][cc], a[3][cc]);
                *(float4*)&Hs[c0 + cc][r0] = v;
            }
            // next iteration's wait+sync orders these stores before reads
        } else {
            #pragma unroll
            for (int rr = 0; rr < 4; rr++) {
                float4 v = make_float4(a[rr][0], a[rr][1], a[rr][2], a[rr][3]);
                *(float4*)&out[(row0 + r0 + rr) * 64 + c0] = v;
                if (task > 0) *(float4*)&Ws[1][r0 + rr][c0] = v;   // K tile [j][d]
            }
            if (task > 0) {
                #pragma unroll
                for (int q = 0; q < 8; q++) {
                    int idx = tid + q * 256;
                    Hs[idx >> 5][idx & 31] = vreg[q];              // V tile [j][e]
                }
            }
            __syncthreads();
        }
    }

    if (task == 0) return;

    // ---------------- fused blocksum: O_b = K^T V ----------
    const int m = task - 1;
    const int d1 = tid & 63;
    const int gg = tid >> 6;   // 0..3 -> e0 = gg*8
    u64 acc2[4] = {0ULL, 0ULL, 0ULL, 0ULL};

    #pragma unroll 8
    for (int j = 0; j < CBLK; j++) {
        float kv = Ws[1][j][d1];
        u64 kd = pk2(kv, kv);
        ulonglong2 va = *(const ulonglong2*)&Hs[j][gg * 8];
        ulonglong2 vb = *(const ulonglong2*)&Hs[j][gg * 8 + 4];
        ffma2(acc2[0], kd, va.x); ffma2(acc2[1], kd, va.y);
        ffma2(acc2[2], kd, vb.x); ffma2(acc2[3], kd, vb.y);
    }
    float a2[8];
    upk2(acc2[0], a2[0], a2[1]); upk2(acc2[1], a2[2], a2[3]);
    upk2(acc2[2], a2[4], a2[5]); upk2(acc2[3], a2[6], a2[7]);
    const int blk = c_OOFF[m] + (row0 >> 6);
    float* o = &g_O[blk * 2048 + d1 * 32 + gg * 8];
    *(float4*)o       = make_float4(a2[0], a2[1], a2[2], a2[3]);
    *(float4*)(o + 4) = make_float4(a2[4], a2[5], a2[6], a2[7]);
}

// ---------------------------------------------------------------------------
// Kernel 2: warp-parallel exclusive scan (blocks 0..1023) + tile binary
// searches (1024..1027) + output zero-fill (1028..1155).
// ---------------------------------------------------------------------------
__global__ void __launch_bounds__(256) scan_search_kernel(float* __restrict__ out)
{
    const int blk = blockIdx.x;
    if (blk < 1024) {
        const int gw   = blk * 8 + (threadIdx.x >> 5);   // 0..8191
        const int lane = threadIdx.x & 31;
        const int m    = gw >> 11;
        const int el   = gw & 2047;
        const int nb   = c_NB[m];
        const int q    = nb >> 5;                        // 2,3,4,2
        const float* src = &g_O[c_OOFF[m] * 2048 + el];
        float* dst       = &g_S[c_SOFF[m] * 2048 + el];
        const int b0 = lane * q;

        float v[4];
        #pragma unroll
        for (int b = 0; b < 4; b++)
            v[b] = (b < q) ? src[(b0 + b) * 2048] : 0.0f;
        float s = 0.0f;
        #pragma unroll
        for (int b = 0; b < 4; b++) if (b < q) s += v[b];

        float incl = s;
        #pragma unroll
        for (int off = 1; off < 32; off <<= 1) {
            float t = __shfl_up_sync(0xffffffffu, incl, off);
            if (lane >= off) incl += t;
        }
        float run = incl - s;

        #pragma unroll
        for (int b = 0; b < 4; b++) {
            if (b < q) { dst[(b0 + b) * 2048] = run; run += v[b]; }
        }
        if (lane == 31) dst[nb * 2048] = run;
    } else if (blk < 1028) {
        const int sid = (blk - 1024) * 256 + threadIdx.x;   // 0..1023
        const int tile = sid >> 3;
        const int m    = (sid >> 1) & 3;
        const int w    = sid & 1;
        const float target = g_t2[tile * 32 + (w ? 31 : 0)];
        const int ko = c_KOFF[m];
        int lo = 0, hi = c_T2[m];
        while (lo < hi) {
            int mid = (lo + hi) >> 1;
            if (g_t2[ko + mid] <= target) lo = mid + 1; else hi = mid;
        }
        g_cnt[tile][m][w] = lo;
    } else {
        const int idx = (blk - 1028) * 256 + threadIdx.x;   // float4 index
        if (idx < T1 * 32 / 4)
            ((float4*)out)[idx] = make_float4(0.f, 0.f, 0.f, 0.f);
    }
}

// ---------------------------------------------------------------------------
// Kernel 3: query kernel, pair-packed, atomicAdd epilogue (R13 proven).
// ---------------------------------------------------------------------------
__global__ void __launch_bounds__(256) query_kernel(
    const float* __restrict__ m1, const float* __restrict__ m2,
    const float* __restrict__ m3, const float* __restrict__ m4,
    float* __restrict__ out)
{
    __shared__ float Qs [32][68];    // [i][d]
    __shared__ float Ss2[32][68];    // state transposed [e][d]
    __shared__ float Ks [64][68];    // keys [j][d]
    __shared__ float Vs2[32][68];    // values transposed [e][j]
    __shared__ float sc [32][68];    // scores [i][j]
    __shared__ float t2s[64];

    const int tid = threadIdx.x;
    const int i   = tid & 31;        // query (lane)
    const int g   = tid >> 5;        // warp
    const int e0  = g * 4;           // e-slice for matvec/accumulate
    const int j0  = g * 8;           // j-slice for scores
    const int tile = blockIdx.x;
    const int m    = blockIdx.y;
    const int i0   = tile * 32;

    const float* X;
    if (m == 0) X = m1; else if (m == 1) X = m2; else if (m == 2) X = m3; else X = m4;
    const int ko = c_KOFF[m];

    const int cf = g_cnt[tile][m][0];
    const int cl = g_cnt[tile][m][1];
    const int B0 = cf >> 6;
    const int jstart = B0 << 6;
    const int jend = cl;

    for (int idx = tid; idx < 2048; idx += 256) {
        int r = idx >> 6, d = idx & 63;
        Qs[r][d] = g_Q[(i0 + r) * 64 + d];
    }
    const float* Sp = &g_S[(c_SOFF[m] + B0) * 2048];
    for (int idx = tid; idx < 2048; idx += 256) {
        int d = idx >> 5, e = idx & 31;
        Ss2[e][d] = Sp[idx];
    }
    const float t1i = g_t2[i0 + i];
    __syncthreads();

    u64 accp[4] = {0ULL, 0ULL, 0ULL, 0ULL};

    // state matvec: acc[e] += sum_d Q[i][d] * S[d][e], packed over d
    #pragma unroll 4
    for (int dp = 0; dp < 16; dp++) {
        ulonglong2 q2 = *(const ulonglong2*)&Qs[i][dp * 4];
        #pragma unroll
        for (int e = 0; e < 4; e++) {
            ulonglong2 s2 = *(const ulonglong2*)&Ss2[e0 + e][dp * 4];
            ffma2(accp[e], q2.x, s2.x);
            ffma2(accp[e], q2.y, s2.y);
        }
    }

    for (int jc = jstart; jc < jend; jc += 64) {
        const int nj = min(64, jend - jc);
        __syncthreads();
        for (int idx = tid; idx < 4096; idx += 256) {
            int j = idx >> 6, d = idx & 63;
            Ks[j][d] = (j < nj) ? g_K[(ko + jc + j) * 64 + d] : 0.0f;
        }
        for (int idx = tid; idx < 2048; idx += 256) {
            int j = idx >> 5, e = idx & 31;
            Vs2[e][j] = (j < nj) ? X[(jc + j) * 64 + e] : 0.0f;
        }
        if (tid < 64) t2s[tid] = (tid < nj) ? g_t2[ko + jc + tid] : 3.0e38f;
        __syncthreads();

        u64 sp[8];
        #pragma unroll
        for (int jj = 0; jj < 8; jj++) sp[jj] = 0ULL;
        #pragma unroll 4
        for (int dp = 0; dp < 16; dp++) {
            ulonglong2 q2 = *(const ulonglong2*)&Qs[i][dp * 4];
            #pragma unroll
            for (int jj = 0; jj < 8; jj++) {
                ulonglong2 k2 = *(const ulonglong2*)&Ks[j0 + jj][dp * 4];
                ffma2(sp[jj], q2.x, k2.x);
                ffma2(sp[jj], q2.y, k2.y);
            }
        }
        #pragma unroll
        for (int jj = 0; jj < 8; jj++) {
            float slo, shi;
            upk2(sp[jj], slo, shi);
            float s = slo + shi;
            sc[i][j0 + jj] = (t2s[j0 + jj] <= t1i) ? s : 0.0f;
        }
        __syncthreads();

        #pragma unroll 4
        for (int jp = 0; jp < 16; jp++) {
            ulonglong2 s2 = *(const ulonglong2*)&sc[i][jp * 4];
            #pragma unroll
            for (int e = 0; e < 4; e++) {
                ulonglong2 v2 = *(const ulonglong2*)&Vs2[e0 + e][jp * 4];
                ffma2(accp[e], s2.x, v2.x);
                ffma2(accp[e], s2.y, v2.y);
            }
        }
    }

    float* op = &out[(i0 + i) * 32 + e0];
    #pragma unroll
    for (int e = 0; e < 4; e++) {
        float lo, hi;
        upk2(accp[e], lo, hi);
        atomicAdd(op + e, lo + hi);
    }
}

// ---------------------------------------------------------------------------
extern "C" void kernel_launch(void* const* d_in, const int* in_sizes, int n_in,
                              void* d_out, int out_size)
{
    const float* m1   = (const float*)d_in[0];
    const float* m2   = (const float*)d_in[1];
    const float* m3   = (const float*)d_in[2];
    const float* m4   = (const float*)d_in[3];
    const float* WQ_w = (const float*)d_in[4];
    const float* WQ_b = (const float*)d_in[5];
    const float* WK_w = (const float*)d_in[6];
    const float* WK_b = (const float*)d_in[7];
    float* out = (float*)d_out;

    mlp_kernel<<<dim3(128, 5), 256>>>(m1, m2, m3, m4, WQ_w, WQ_b, WK_w, WK_b);
    scan_search_kernel<<<1156, 256>>>(out);
    query_kernel<<<dim3(NTILE, 4), 256>>>(m1, m2, m3, m4, out);
}